// round 13
// baseline (speedup 1.0000x reference)
#include <cuda_runtime.h>

// CropAndResize: image (8,256,200,200) f32 NCHW, boxes (512,4) [y1,x1,y2,x2],
// box_indices (512,) int32 -> out (512,256,14,14) f32. Bilinear, extrap 0.
//
// R13: R12 skeleton (sorted boxes, cchunk-major, fixed position/thread,
// 2-channel inner step) + in-block prefetch.global.L2 of the lines the box
// will gather 2 iterations ahead -> DRAM misses become full-line sequential
// bursts instead of scattered 32B sectors.

#define IH 200
#define IW 200
#define CROP 14
#define NCH 256
#define NBOX 512
#define NIMG 8
#define PLANE (IH * IW)
#define POS (CROP * CROP)          // 196
#define CCHUNK 64                  // channels per block
#define NCHUNKS (NCH / CCHUNK)     // 4
#define TPB (2 * POS)              // 392: sub = tid/196 in {0,1}
#define STRIP 32                   // channels per thread strip
#define LA 4                       // prefetch lookahead (channels)

__device__ int d_perm[NBOX];       // box ids sorted by image index

__global__ __launch_bounds__(NBOX) void sort_boxes_kernel(
    const int* __restrict__ box_idx)
{
    __shared__ int cnt[NIMG];
    __shared__ int off[NIMG + 1];
    const int tid = threadIdx.x;
    if (tid < NIMG) cnt[tid] = 0;
    __syncthreads();
    const int b = box_idx[tid];
    atomicAdd(&cnt[b], 1);
    __syncthreads();
    if (tid == 0) {
        int s = 0;
        for (int i = 0; i < NIMG; ++i) { off[i] = s; s += cnt[i]; }
        off[NIMG] = s;
    }
    __syncthreads();
    const int pos = atomicAdd(&off[b], 1);   // bucket-internal order irrelevant
    d_perm[pos] = tid;
}

__global__ __launch_bounds__(TPB, 4) void crop_resize_kernel(
    const float* __restrict__ image,
    const float* __restrict__ boxes,
    const int*   __restrict__ box_idx,
    float*       __restrict__ out)
{
    __shared__ int   sy0[CROP], sy1[CROP], sx0[CROP], sx1[CROP];
    __shared__ float sly[CROP], slx[CROP];
    __shared__ unsigned svy[CROP], svx[CROP];
    __shared__ int sn;
    __shared__ const float* splane;

    const int cchunk = blockIdx.x / NBOX;   // cchunk-major + sorted boxes:
    const int spos   = blockIdx.x % NBOX;   // small L2 working set
    const int tid    = threadIdx.x;

    if (tid == 0) {
        const int n = d_perm[spos];
        sn = n;
        splane = image + (size_t)box_idx[n] * NCH * PLANE;
    }
    __syncthreads();
    const int n = sn;

    // Per-box interpolation coefficients: threads 0..13 x-axis, 14..27 y-axis.
    if (tid < 2 * CROP) {
        const bool isx = (tid < CROP);
        const int  k   = isx ? tid : tid - CROP;
        const float a1 = boxes[n * 4 + (isx ? 1 : 0)];
        const float a2 = boxes[n * 4 + (isx ? 3 : 2)];
        const float D  = isx ? (float)(IW - 1) : (float)(IH - 1);
        const float scale = (a2 - a1) * D * (1.0f / (CROP - 1));
        const float v  = a1 * D + (float)k * scale;
        const unsigned valid = (v >= 0.0f) && (v <= D);
        const float fl = floorf(v);
        const float ce = ceilf(v);
        const float l  = v - fl;
        const int i0 = (int)fminf(fmaxf(fl, 0.0f), D);
        const int i1 = (int)fminf(fmaxf(ce, 0.0f), D);
        if (isx) { sx0[k] = i0; sx1[k] = i1; slx[k] = l; svx[k] = valid; }
        else     { sy0[k] = i0; sy1[k] = i1; sly[k] = l; svy[k] = valid; }
    }
    __syncthreads();

    // Fixed per-thread decode: sub in {0,1} picks a 32-channel strip.
    const int sub = (tid >= POS) ? 1 : 0;
    const int pos = tid - sub * POS;
    const int r   = pos / CROP;
    const int col = pos - r * CROP;

    const int y0 = sy0[r], y1 = sy1[r];
    const int x0 = sx0[col], x1 = sx1[col];
    const float lx = slx[col], ly = sly[r];
    const bool valid = (svy[r] & svx[col]) != 0;

    const int o_tl = y0 * IW + x0;
    const int o_tr = y0 * IW + x1;
    const int o_bl = y1 * IW + x0;
    const int o_br = y1 * IW + x1;

    // ---- Prefetch plan: lines covering [xmin,xmax] for each of 28 rows ----
    // in_x is linear in k -> endpoints bound the x range (handles x2 < x1).
    const int xmin = min(sx0[0], sx0[CROP - 1]);
    const int xmax = max(sx1[0], sx1[CROP - 1]);
    const int lo   = (xmin * 4) >> 7;             // first 128B line in row
    const int nl   = ((xmax * 4 + 3) >> 7) - lo + 1;   // lines per row (<=7)
    const int items = 2 * CROP * nl;              // <= 224

    // This thread's prefetch item(s): item i -> (row i/nl, line lo + i%nl)
    int pf_ofs0 = -1, pf_ofs1 = -1;
    {
        const int i0i = pos;                      // each sub-group: 196 lanes
        if (i0i < items) {
            const int rr = i0i / nl;
            const int ll = i0i - rr * nl;
            const int row = (rr < CROP) ? sy0[rr] : sy1[rr - CROP];
            pf_ofs0 = row * (IW * 4) + (lo + ll) * 128;
        }
        const int i1i = pos + POS;
        if (i1i < items) {
            const int rr = i1i / nl;
            const int ll = i1i - rr * nl;
            const int row = (rr < CROP) ? sy0[rr] : sy1[rr - CROP];
            pf_ofs1 = row * (IW * 4) + (lo + ll) * 128;
        }
    }

    const int cbase = cchunk * CCHUNK + sub * STRIP;
    const float* pl = splane + (size_t)cbase * PLANE;
    const char*  pfb = (const char*)pl;           // prefetch base for strip
    float* outp = out + (size_t)n * NCH * POS + (size_t)cbase * POS + pos;

    if (valid) {
        #pragma unroll 2
        for (int k = 0; k < STRIP; k += 2) {
            // Prefetch channels k+LA, k+LA+1 (full lines, sequential bursts)
            if (k + LA < STRIP) {
                const char* pf = pfb + (size_t)(k + LA) * (PLANE * 4);
                if (pf_ofs0 >= 0) {
                    asm volatile("prefetch.global.L2 [%0];" :: "l"(pf + pf_ofs0));
                    asm volatile("prefetch.global.L2 [%0];" :: "l"(pf + PLANE * 4 + pf_ofs0));
                }
                if (pf_ofs1 >= 0) {
                    asm volatile("prefetch.global.L2 [%0];" :: "l"(pf + pf_ofs1));
                    asm volatile("prefetch.global.L2 [%0];" :: "l"(pf + PLANE * 4 + pf_ofs1));
                }
            }

            const float* p0 = pl;
            const float* p1 = pl + PLANE;
            const float tl0 = __ldg(p0 + o_tl);
            const float tr0 = __ldg(p0 + o_tr);
            const float bl0 = __ldg(p0 + o_bl);
            const float br0 = __ldg(p0 + o_br);
            const float tl1 = __ldg(p1 + o_tl);
            const float tr1 = __ldg(p1 + o_tr);
            const float bl1 = __ldg(p1 + o_bl);
            const float br1 = __ldg(p1 + o_br);

            const float top0 = fmaf(tr0 - tl0, lx, tl0);
            const float bot0 = fmaf(br0 - bl0, lx, bl0);
            const float top1 = fmaf(tr1 - tl1, lx, tl1);
            const float bot1 = fmaf(br1 - bl1, lx, bl1);
            __stcs(outp,       fmaf(bot0 - top0, ly, top0));
            __stcs(outp + POS, fmaf(bot1 - top1, ly, top1));
            pl   += 2 * PLANE;
            outp += 2 * POS;
        }
    } else {
        #pragma unroll 8
        for (int k = 0; k < STRIP; ++k) {
            __stcs(outp, 0.0f);
            outp += POS;
        }
    }
}

extern "C" void kernel_launch(void* const* d_in, const int* in_sizes, int n_in,
                              void* d_out, int out_size)
{
    const float* image   = (const float*)d_in[0];
    const float* boxes   = (const float*)d_in[1];
    const int*   box_idx = (const int*)d_in[2];
    float*       out     = (float*)d_out;

    sort_boxes_kernel<<<1, NBOX>>>(box_idx);
    crop_resize_kernel<<<NCHUNKS * NBOX, TPB>>>(image, boxes, box_idx, out);
}

// round 14
// speedup vs baseline: 1.1696x; 1.1696x over previous
#include <cuda_runtime.h>
#include <cstdint>

// CropAndResize: image (8,256,200,200) f32 NCHW, boxes (512,4) [y1,x1,y2,x2],
// box_indices (512,) int32 -> out (512,256,14,14) f32. Bilinear, extrap 0.
//
// R14: quarter-plane staging, 4 CTAs/SM for load/gather self-staggering.
// Block = (image, channel, quarter): cp.async streams 51 rows sequentially
// into padded SMEM; gather uses global entry lists + x-tables (L1/L2-hot,
// built once by a tiny prep kernel). No smem tables, no per-block math.

#define IH 200
#define IW 200
#define CROP 14
#define NCH 256
#define NBOX 512
#define NIMG 8
#define PLANE (IH * IW)
#define POS (CROP * CROP)          // 196
#define PITCH 204                  // smem row pitch (floats), 816B rows
#define NQ 4                       // row quarters per plane
#define QROWS 50
#define BROWS 51                   // buffer rows (covers y1 partner at q*50+50)
#define MAXBI 128                  // max boxes per image
#define CAP (MAXBI * CROP)         // entry capacity per (image, quarter)
#define TPB 448                    // 32 entry-groups x 14 cols
#define EGRP 32
#define CPR 50                     // 16B chunks per image row

__device__ int   d_nbox[NIMG];
__device__ int   d_nent[NIMG * NQ];
__device__ uint2 d_xtab[NIMG * MAXBI * CROP];   // {x0 | vx<<8, lx}
__device__ uint2 d_ent[NIMG * NQ * CAP];        // {nid|slot<<9|o<<16|dy<<22|vy<<23|r<<24, ly}

__global__ __launch_bounds__(NBOX) void prep_kernel(
    const float* __restrict__ boxes,
    const int*   __restrict__ box_idx)
{
    const int n = threadIdx.x;
    if (n < NIMG) d_nbox[n] = 0;
    if (n < NIMG * NQ) d_nent[n] = 0;
    __syncthreads();

    const int img  = box_idx[n];
    const int slot = atomicAdd(&d_nbox[img], 1);   // order irrelevant
    const float4 bq = ((const float4*)boxes)[n];   // y1,x1,y2,x2
    const float ys = (bq.z - bq.x) * (float)(IH - 1) * (1.0f / (CROP - 1));
    const float xs = (bq.w - bq.y) * (float)(IW - 1) * (1.0f / (CROP - 1));

    #pragma unroll
    for (int k = 0; k < CROP; ++k) {
        {   // x table (per box, per crop-col)
            const float v  = bq.y * (float)(IW - 1) + (float)k * xs;
            const float fl = floorf(v);
            const int x0 = (int)fminf(fmaxf(fl, 0.0f), (float)(IW - 1));
            const unsigned vx = (v >= 0.0f && v <= (float)(IW - 1)) ? 1u : 0u;
            d_xtab[(img * MAXBI + slot) * CROP + k] =
                make_uint2((unsigned)x0 | (vx << 8), __float_as_uint(v - fl));
        }
        {   // y row -> entry in owning quarter's list
            const float v  = bq.x * (float)(IH - 1) + (float)k * ys;
            const float fl = floorf(v);
            const int y0 = (int)fminf(fmaxf(fl, 0.0f), (float)(IH - 1));
            const int q  = y0 / QROWS;                   // 0..3
            const int o  = y0 - q * QROWS;               // 0..49
            const unsigned dy = (y0 < IH - 1) ? 1u : 0u;
            const unsigned vy = (v >= 0.0f && v <= (float)(IH - 1)) ? 1u : 0u;
            const int idx = atomicAdd(&d_nent[img * NQ + q], 1);
            d_ent[(img * NQ + q) * CAP + idx] = make_uint2(
                (unsigned)n | ((unsigned)slot << 9) | ((unsigned)o << 16)
                | (dy << 22) | (vy << 23) | ((unsigned)k << 24),
                __float_as_uint(v - fl));
        }
    }
}

#define SM_BYTES (BROWS * PITCH * 4)   // 41616 -> 4 CTAs/SM

__global__ __launch_bounds__(TPB, 4) void crop_resize_kernel(
    const float* __restrict__ image,
    float*       __restrict__ out)
{
    extern __shared__ float plane[];   // BROWS x PITCH, padded

    const int bx  = blockIdx.x;
    const int img = bx >> 10;          // 1024 blocks/image: ch-major, q inner
    const int ch  = (bx >> 2) & 255;
    const int q   = bx & 3;
    const int tid = threadIdx.x;

    // ---- Stage quarter-plane: sequential 16B cp.async, one commit group ----
    // rows q*50 .. q*50+50 (51 rows; 50 for q=3)
    const int nchunk = ((q == 3) ? 50 : 51) * CPR;
    const char* srcb = (const char*)(image + ((size_t)img * NCH + ch) * PLANE
                                           + (size_t)q * QROWS * IW);
    const uint32_t smem_b = (uint32_t)__cvta_generic_to_shared(plane);
    #pragma unroll 2
    for (int i = tid; i < nchunk; i += TPB) {
        const int row = i / CPR;
        const int c16 = i - row * CPR;
        asm volatile("cp.async.cg.shared.global [%0], [%1], 16;"
                     :: "r"(smem_b + row * (PITCH * 4) + c16 * 16),
                        "l"(srcb + row * (IW * 4) + c16 * 16));
    }
    asm volatile("cp.async.commit_group;");

    // Zero row pads (x0=199 pair reads land at col 200; lx=0 there).
    if (tid < BROWS) {
        float4* pad = (float4*)(plane + tid * PITCH + IW);
        *pad = make_float4(0.f, 0.f, 0.f, 0.f);
    }

    const int ne = d_nent[img * NQ + q];
    const uint2* gent = d_ent + (img * NQ + q) * CAP;
    const uint2* gxt  = d_xtab + (size_t)img * MAXBI * CROP;

    // Fixed per-thread decode: entry-group, crop-col
    const int e0  = tid / CROP;        // 0..31
    const int col = tid - e0 * CROP;   // 0..13
    float* outb = out + (size_t)ch * POS + col;

    asm volatile("cp.async.wait_group 0;");
    __syncthreads();

    // ---- Gather: zero wasted iterations, tables via L1-hot __ldg ----
    for (int e = e0; e < ne; e += EGRP) {
        const uint2 E = __ldg(gent + e);
        const unsigned nid  = E.x & 511u;
        const unsigned slot = (E.x >> 9) & 127u;
        const int      o    = (E.x >> 16) & 63;
        const unsigned dy   = (E.x >> 22) & 1u;
        const unsigned vy   = (E.x >> 23) & 1u;
        const unsigned r    = (E.x >> 24) & 15u;
        const float    ly   = __uint_as_float(E.y);

        const uint2 tx = __ldg(gxt + slot * CROP + col);
        const int   x0 = tx.x & 255;
        const float lx = __uint_as_float(tx.y);

        const float* r0 = plane + o * PITCH + x0;
        const float* r1 = r0 + dy * PITCH;
        const float tl = r0[0], tr = r0[1];
        const float bl = r1[0], br = r1[1];
        const float top = fmaf(tr - tl, lx, tl);
        const float bot = fmaf(br - bl, lx, bl);
        float val = fmaf(bot - top, ly, top);
        if (!(vy & (tx.x >> 8) & 1u)) val = 0.0f;

        __stcs(outb + (size_t)nid * (NCH * POS) + r * CROP, val);
    }
}

extern "C" void kernel_launch(void* const* d_in, const int* in_sizes, int n_in,
                              void* d_out, int out_size)
{
    const float* image   = (const float*)d_in[0];
    const float* boxes   = (const float*)d_in[1];
    const int*   box_idx = (const int*)d_in[2];
    float*       out     = (float*)d_out;

    prep_kernel<<<1, NBOX>>>(boxes, box_idx);
    crop_resize_kernel<<<NIMG * NCH * NQ, TPB, SM_BYTES>>>(image, out);
}